// round 4
// baseline (speedup 1.0000x reference)
#include <cuda_runtime.h>
#include <cuda_fp16.h>
#include <cstdint>

// GridEncoder (instant-ngp style), D=3, L=16, C=2, H=16, PLS=2, log2_hashmap=19,
// align_corners=false.
//
// R4: width-matched fused gathers on the half2 table:
//   m=1 (diff==1, 50%): one LDG.64  (exactly the 8B pair)
//   m=2 (diff<4,  25%): one LDG.128 (16B quad)
//   m>=3        (25%): two LDG.32
// -> same 5 lane-loads/pl as R3 but ~40B/pl instead of 56B/pl.

#define NLEV 16
#define PRIME1 2654435761u
#define PRIME2 805459861u
#define HASH_MASK 0x7FFFFu
#define TOTAL_PARAMS 7131240

__device__ __align__(16) __half2 g_embh[TOTAL_PARAMS];   // 28.5 MB scratch

__constant__ uint32_t c_off[NLEV] = {
    0u, 4920u, 40864u, 315496u,
    839784u, 1364072u, 1888360u, 2412648u,
    2936936u, 3461224u, 3985512u, 4509800u,
    5034088u, 5558376u, 6082664u, 6606952u
};
__constant__ float c_scale[NLEV] = {
    15.f, 31.f, 63.f, 127.f, 255.f, 511.f, 1023.f, 2047.f,
    4095.f, 8191.f, 16383.f, 32767.f, 65535.f, 131071.f, 262143.f, 524287.f
};
__constant__ uint32_t c_base[3] = {17u, 33u, 65u};

// fp32 [N,2] -> half2 [N], 2 entries per thread (float4 reads)
__global__ void __launch_bounds__(256)
convert_kernel(const float4* __restrict__ emb, int npairs)
{
    int i = blockIdx.x * blockDim.x + threadIdx.x;
    if (i < npairs) {
        float4 v = __ldg(&emb[i]);
        g_embh[2 * i + 0] = __floats2half2_rn(v.x, v.y);
        g_embh[2 * i + 1] = __floats2half2_rn(v.z, v.w);
    }
}

__device__ __forceinline__ float2 h2f(uint32_t h)
{
    __half2 v = *reinterpret_cast<__half2*>(&h);
    return __half22float2(v);
}

// Load embeddings for an x-adjacent corner pair, fetching only needed bytes.
__device__ __forceinline__ void load_pair(uint32_t iA, uint32_t iB,
                                          float2& ea, float2& eb)
{
    uint32_t diff = iA ^ iB;
    if (diff == 1u) {
        // same 8B-aligned pair: one LDG.64
        uint2 d = __ldg(reinterpret_cast<const uint2*>(g_embh + (iA & ~1u)));
        uint32_t ha = (iA & 1u) ? d.y : d.x;
        uint32_t hb = (iA & 1u) ? d.x : d.y;
        ea = h2f(ha);
        eb = h2f(hb);
    } else if (diff < 4u) {
        // same 16B-aligned quad: one LDG.128
        uint4 q = __ldg(reinterpret_cast<const uint4*>(g_embh + (iA & ~3u)));
        uint32_t ka = iA & 3u, kb = iB & 3u;
        uint32_t a_lo = (ka & 1u) ? q.y : q.x;
        uint32_t a_hi = (ka & 1u) ? q.w : q.z;
        uint32_t b_lo = (kb & 1u) ? q.y : q.x;
        uint32_t b_hi = (kb & 1u) ? q.w : q.z;
        ea = h2f((ka & 2u) ? a_hi : a_lo);
        eb = h2f((kb & 2u) ? b_hi : b_lo);
    } else {
        ea = h2f(__ldg(reinterpret_cast<const uint32_t*>(g_embh + iA)));
        eb = h2f(__ldg(reinterpret_cast<const uint32_t*>(g_embh + iB)));
    }
}

__global__ void __launch_bounds__(256)
grid_encode_kernel(const float* __restrict__ in,
                   float2* __restrict__ out,
                   int B)
{
    int t = blockIdx.x * blockDim.x + threadIdx.x;
    int p = t >> 4;           // point index
    int l = t & 15;           // level index
    if (p >= B) return;

    // map inputs from [-1,1] to [0,1]
    float x = (in[p * 3 + 0] + 1.0f) * 0.5f;
    float y = (in[p * 3 + 1] + 1.0f) * 0.5f;
    float z = (in[p * 3 + 2] + 1.0f) * 0.5f;

    float scale = c_scale[l];
    float px = fmaf(x, scale, 0.5f);
    float py = fmaf(y, scale, 0.5f);
    float pz = fmaf(z, scale, 0.5f);

    float fx = floorf(px), fy = floorf(py), fz = floorf(pz);
    uint32_t gx = (uint32_t)fx, gy = (uint32_t)fy, gz = (uint32_t)fz;
    float rx = px - fx, ry = py - fy, rz = pz - fz;

    uint32_t off = c_off[l];

    uint32_t i00a, i00b, i10a, i10b, i01a, i01b, i11a, i11b;
    if (l >= 3) {
        uint32_t x0 = gx,              x1 = gx + 1u;
        uint32_t y0 = gy * PRIME1,     y1 = (gy + 1u) * PRIME1;
        uint32_t z0 = gz * PRIME2,     z1 = (gz + 1u) * PRIME2;
        uint32_t h00 = y0 ^ z0, h10 = y1 ^ z0, h01 = y0 ^ z1, h11 = y1 ^ z1;
        i00a = ((x0 ^ h00) & HASH_MASK) + off;
        i00b = ((x1 ^ h00) & HASH_MASK) + off;
        i10a = ((x0 ^ h10) & HASH_MASK) + off;
        i10b = ((x1 ^ h10) & HASH_MASK) + off;
        i01a = ((x0 ^ h01) & HASH_MASK) + off;
        i01b = ((x1 ^ h01) & HASH_MASK) + off;
        i11a = ((x0 ^ h11) & HASH_MASK) + off;
        i11b = ((x1 ^ h11) & HASH_MASK) + off;
    } else {
        uint32_t base = c_base[l];
        uint32_t b2 = base * base;
        uint32_t y0 = gy * base, y1 = y0 + base;
        uint32_t z0 = gz * b2,   z1 = z0 + b2;
        uint32_t s00 = y0 + z0 + off, s10 = y1 + z0 + off;
        uint32_t s01 = y0 + z1 + off, s11 = y1 + z1 + off;
        i00a = gx + s00; i00b = i00a + 1u;
        i10a = gx + s10; i10b = i10a + 1u;
        i01a = gx + s01; i01b = i01a + 1u;
        i11a = gx + s11; i11b = i11a + 1u;
    }

    float2 e0, e1, e2c, e3, e4c, e5, e6, e7;
    load_pair(i00a, i00b, e0,  e1);
    load_pair(i10a, i10b, e2c, e3);
    load_pair(i01a, i01b, e4c, e5);
    load_pair(i11a, i11b, e6,  e7);

    float wx0 = 1.0f - rx, wx1 = rx;
    float wy0 = 1.0f - ry, wy1 = ry;
    float wz0 = 1.0f - rz, wz1 = rz;

    float w00 = wy0 * wz0, w10 = wy1 * wz0, w01 = wy0 * wz1, w11 = wy1 * wz1;

    float w0 = wx0 * w00, w1 = wx1 * w00;
    float w2 = wx0 * w10, w3 = wx1 * w10;
    float w4 = wx0 * w01, w5 = wx1 * w01;
    float w6 = wx0 * w11, w7 = wx1 * w11;

    float a0 = w0 * e0.x;            float a1 = w0 * e0.y;
    a0 = fmaf(w1, e1.x,  a0);        a1 = fmaf(w1, e1.y,  a1);
    a0 = fmaf(w2, e2c.x, a0);        a1 = fmaf(w2, e2c.y, a1);
    a0 = fmaf(w3, e3.x,  a0);        a1 = fmaf(w3, e3.y,  a1);
    a0 = fmaf(w4, e4c.x, a0);        a1 = fmaf(w4, e4c.y, a1);
    a0 = fmaf(w5, e5.x,  a0);        a1 = fmaf(w5, e5.y,  a1);
    a0 = fmaf(w6, e6.x,  a0);        a1 = fmaf(w6, e6.y,  a1);
    a0 = fmaf(w7, e7.x,  a0);        a1 = fmaf(w7, e7.y,  a1);

    out[p * 16 + l] = make_float2(a0, a1);
}

extern "C" void kernel_launch(void* const* d_in, const int* in_sizes, int n_in,
                              void* d_out, int out_size) {
    const float*  inputs = (const float*)d_in[0];       // [B, 3]
    const float4* emb4   = (const float4*)d_in[1];      // [N,2] fp32 as pairs-of-rows
    float2*       out    = (float2*)d_out;              // [B, 16] of float2

    int B = in_sizes[0] / 3;

    // 1) convert table fp32 -> half2 (TOTAL_PARAMS is even)
    int npairs = TOTAL_PARAMS / 2;
    convert_kernel<<<(npairs + 255) / 256, 256>>>(emb4, npairs);

    // 2) main encode
    int threads = 256;
    long long total = (long long)B * 16;
    int blocks = (int)((total + threads - 1) / threads);
    grid_encode_kernel<<<blocks, threads>>>(inputs, out, B);
}

// round 5
// speedup vs baseline: 1.0373x; 1.0373x over previous
#include <cuda_runtime.h>
#include <cuda_fp16.h>
#include <cstdint>

// GridEncoder (instant-ngp style), D=3, L=16, C=2, H=16, PLS=2, log2_hashmap=19,
// align_corners=false.
//
// R5: branch-free gather stream on the half2 table.
//   - ea is ALWAYS inside the 16B quad at (iA & ~3): 4 unconditional LDG.128.
//   - eb is in that same quad iff (iA^iB) < 4 (75%); otherwise one predicated
//     LDG.32 (no BSSY). All selection is branchless ALU.

#define NLEV 16
#define PRIME1 2654435761u
#define PRIME2 805459861u
#define HASH_MASK 0x7FFFFu
#define TOTAL_PARAMS 7131240

__device__ __align__(16) __half2 g_embh[TOTAL_PARAMS];   // 28.5 MB scratch

__constant__ uint32_t c_off[NLEV] = {
    0u, 4920u, 40864u, 315496u,
    839784u, 1364072u, 1888360u, 2412648u,
    2936936u, 3461224u, 3985512u, 4509800u,
    5034088u, 5558376u, 6082664u, 6606952u
};
__constant__ float c_scale[NLEV] = {
    15.f, 31.f, 63.f, 127.f, 255.f, 511.f, 1023.f, 2047.f,
    4095.f, 8191.f, 16383.f, 32767.f, 65535.f, 131071.f, 262143.f, 524287.f
};
__constant__ uint32_t c_base[3] = {17u, 33u, 65u};

// fp32 [N,2] -> half2 [N], 2 entries per thread (float4 reads)
__global__ void __launch_bounds__(256)
convert_kernel(const float4* __restrict__ emb, int npairs)
{
    int i = blockIdx.x * blockDim.x + threadIdx.x;
    if (i < npairs) {
        float4 v = __ldg(&emb[i]);
        g_embh[2 * i + 0] = __floats2half2_rn(v.x, v.y);
        g_embh[2 * i + 1] = __floats2half2_rn(v.z, v.w);
    }
}

__device__ __forceinline__ uint32_t pick4(uint4 q, uint32_t k)
{
    uint32_t lo = (k & 1u) ? q.y : q.x;
    uint32_t hi = (k & 1u) ? q.w : q.z;
    return (k & 2u) ? hi : lo;
}

__device__ __forceinline__ float2 h2f(uint32_t h)
{
    __half2 v = *reinterpret_cast<__half2*>(&h);
    return __half22float2(v);
}

__global__ void __launch_bounds__(256)
grid_encode_kernel(const float* __restrict__ in,
                   float2* __restrict__ out,
                   int B)
{
    int t = blockIdx.x * blockDim.x + threadIdx.x;
    int p = t >> 4;           // point index
    int l = t & 15;           // level index
    if (p >= B) return;

    // map inputs from [-1,1] to [0,1]
    float x = (in[p * 3 + 0] + 1.0f) * 0.5f;
    float y = (in[p * 3 + 1] + 1.0f) * 0.5f;
    float z = (in[p * 3 + 2] + 1.0f) * 0.5f;

    float scale = c_scale[l];
    float px = fmaf(x, scale, 0.5f);
    float py = fmaf(y, scale, 0.5f);
    float pz = fmaf(z, scale, 0.5f);

    float fx = floorf(px), fy = floorf(py), fz = floorf(pz);
    uint32_t gx = (uint32_t)fx, gy = (uint32_t)fy, gz = (uint32_t)fz;
    float rx = px - fx, ry = py - fy, rz = pz - fz;

    uint32_t off = c_off[l];

    uint32_t iA0, iB0, iA1, iB1, iA2, iB2, iA3, iB3;
    if (l >= 3) {
        uint32_t x0 = gx,              x1 = gx + 1u;
        uint32_t y0 = gy * PRIME1,     y1 = (gy + 1u) * PRIME1;
        uint32_t z0 = gz * PRIME2,     z1 = (gz + 1u) * PRIME2;
        uint32_t h00 = y0 ^ z0, h10 = y1 ^ z0, h01 = y0 ^ z1, h11 = y1 ^ z1;
        iA0 = ((x0 ^ h00) & HASH_MASK) + off;
        iB0 = ((x1 ^ h00) & HASH_MASK) + off;
        iA1 = ((x0 ^ h10) & HASH_MASK) + off;
        iB1 = ((x1 ^ h10) & HASH_MASK) + off;
        iA2 = ((x0 ^ h01) & HASH_MASK) + off;
        iB2 = ((x1 ^ h01) & HASH_MASK) + off;
        iA3 = ((x0 ^ h11) & HASH_MASK) + off;
        iB3 = ((x1 ^ h11) & HASH_MASK) + off;
    } else {
        uint32_t base = c_base[l];
        uint32_t b2 = base * base;
        uint32_t y0 = gy * base, y1 = y0 + base;
        uint32_t z0 = gz * b2,   z1 = z0 + b2;
        iA0 = gx + y0 + z0 + off; iB0 = iA0 + 1u;
        iA1 = gx + y1 + z0 + off; iB1 = iA1 + 1u;
        iA2 = gx + y0 + z1 + off; iB2 = iA2 + 1u;
        iA3 = gx + y1 + z1 + off; iB3 = iA3 + 1u;
    }

    // 4 unconditional quad gathers (each quad contains its pair's A entry)
    const uint4* q0p = reinterpret_cast<const uint4*>(g_embh + (iA0 & ~3u));
    const uint4* q1p = reinterpret_cast<const uint4*>(g_embh + (iA1 & ~3u));
    const uint4* q2p = reinterpret_cast<const uint4*>(g_embh + (iA2 & ~3u));
    const uint4* q3p = reinterpret_cast<const uint4*>(g_embh + (iA3 & ~3u));
    uint4 q0 = __ldg(q0p);
    uint4 q1 = __ldg(q1p);
    uint4 q2 = __ldg(q2p);
    uint4 q3 = __ldg(q3p);

    // predicated tail loads for B entries outside their pair's quad (25%)
    bool far0 = (iA0 ^ iB0) >= 4u;
    bool far1 = (iA1 ^ iB1) >= 4u;
    bool far2 = (iA2 ^ iB2) >= 4u;
    bool far3 = (iA3 ^ iB3) >= 4u;
    uint32_t m0 = 0u, m1 = 0u, m2 = 0u, m3 = 0u;
    if (far0) m0 = __ldg(reinterpret_cast<const uint32_t*>(g_embh + iB0));
    if (far1) m1 = __ldg(reinterpret_cast<const uint32_t*>(g_embh + iB1));
    if (far2) m2 = __ldg(reinterpret_cast<const uint32_t*>(g_embh + iB2));
    if (far3) m3 = __ldg(reinterpret_cast<const uint32_t*>(g_embh + iB3));

    // branchless extraction
    uint32_t hA0 = pick4(q0, iA0 & 3u), hA1 = pick4(q1, iA1 & 3u);
    uint32_t hA2 = pick4(q2, iA2 & 3u), hA3 = pick4(q3, iA3 & 3u);
    uint32_t hB0 = far0 ? m0 : pick4(q0, iB0 & 3u);
    uint32_t hB1 = far1 ? m1 : pick4(q1, iB1 & 3u);
    uint32_t hB2 = far2 ? m2 : pick4(q2, iB2 & 3u);
    uint32_t hB3 = far3 ? m3 : pick4(q3, iB3 & 3u);

    float2 e0 = h2f(hA0), e1 = h2f(hB0);
    float2 e2 = h2f(hA1), e3 = h2f(hB1);
    float2 e4 = h2f(hA2), e5 = h2f(hB2);
    float2 e6 = h2f(hA3), e7 = h2f(hB3);

    float wx0 = 1.0f - rx, wx1 = rx;
    float wy0 = 1.0f - ry, wy1 = ry;
    float wz0 = 1.0f - rz, wz1 = rz;

    float w00 = wy0 * wz0, w10 = wy1 * wz0, w01 = wy0 * wz1, w11 = wy1 * wz1;

    float a0, a1;
    a0 = (wx0 * w00) * e0.x;                 a1 = (wx0 * w00) * e0.y;
    a0 = fmaf(wx1 * w00, e1.x, a0);          a1 = fmaf(wx1 * w00, e1.y, a1);
    a0 = fmaf(wx0 * w10, e2.x, a0);          a1 = fmaf(wx0 * w10, e2.y, a1);
    a0 = fmaf(wx1 * w10, e3.x, a0);          a1 = fmaf(wx1 * w10, e3.y, a1);
    a0 = fmaf(wx0 * w01, e4.x, a0);          a1 = fmaf(wx0 * w01, e4.y, a1);
    a0 = fmaf(wx1 * w01, e5.x, a0);          a1 = fmaf(wx1 * w01, e5.y, a1);
    a0 = fmaf(wx0 * w11, e6.x, a0);          a1 = fmaf(wx0 * w11, e6.y, a1);
    a0 = fmaf(wx1 * w11, e7.x, a0);          a1 = fmaf(wx1 * w11, e7.y, a1);

    out[p * 16 + l] = make_float2(a0, a1);
}

extern "C" void kernel_launch(void* const* d_in, const int* in_sizes, int n_in,
                              void* d_out, int out_size) {
    const float*  inputs = (const float*)d_in[0];       // [B, 3]
    const float4* emb4   = (const float4*)d_in[1];      // [N,2] fp32 viewed as float4
    float2*       out    = (float2*)d_out;              // [B, 16] of float2

    int B = in_sizes[0] / 3;

    // 1) convert table fp32 -> half2 (TOTAL_PARAMS is even)
    int npairs = TOTAL_PARAMS / 2;
    convert_kernel<<<(npairs + 255) / 256, 256>>>(emb4, npairs);

    // 2) main encode
    int threads = 256;
    long long total = (long long)B * 16;
    int blocks = (int)((total + threads - 1) / threads);
    grid_encode_kernel<<<blocks, threads>>>(inputs, out, B);
}

// round 6
// speedup vs baseline: 1.1249x; 1.0845x over previous
#include <cuda_runtime.h>
#include <cuda_fp16.h>
#include <cstdint>

// GridEncoder (instant-ngp style), D=3, L=16, C=2, H=16, PLS=2, log2_hashmap=19,
// align_corners=false.
//
// R6 = R3 (best) + dense-level pair table:
//   - hash levels (l>=3): per x-pair, diff<4 (75%) -> one LDG.128 quad;
//     else 2x LDG.32  (R3 structure, proven fastest)
//   - dense levels (l<3): pairs always index-adjacent -> one LDG.64 from a
//     duplicated pair table P[i]=(E[i],E[i+1]); no far path, no inner branch.
//   - convert kernel vectorized (uint4 stores).

#define NLEV 16
#define PRIME1 2654435761u
#define PRIME2 805459861u
#define HASH_MASK 0x7FFFFu
#define TOTAL_PARAMS 7131240
#define DENSE_TOTAL 839784      // c_off[3] = end of dense region

__device__ __align__(16) __half2 g_embh[TOTAL_PARAMS];   // 28.5 MB half2 table
__device__ __align__(16) uint2   g_paird[DENSE_TOTAL];   // 6.7 MB dense pair table

__constant__ uint32_t c_off[NLEV] = {
    0u, 4920u, 40864u, 315496u,
    839784u, 1364072u, 1888360u, 2412648u,
    2936936u, 3461224u, 3985512u, 4509800u,
    5034088u, 5558376u, 6082664u, 6606952u
};
__constant__ float c_scale[NLEV] = {
    15.f, 31.f, 63.f, 127.f, 255.f, 511.f, 1023.f, 2047.f,
    4095.f, 8191.f, 16383.f, 32767.f, 65535.f, 131071.f, 262143.f, 524287.f
};
__constant__ uint32_t c_base[3] = {17u, 33u, 65u};

// fp32 [N,2] -> half2 [N]; 4 entries per thread, one 16B store.
__global__ void __launch_bounds__(256)
convert_kernel(const float4* __restrict__ emb, int nquads)
{
    int i = blockIdx.x * blockDim.x + threadIdx.x;
    if (i < nquads) {
        float4 v0 = __ldg(&emb[2 * i + 0]);
        float4 v1 = __ldg(&emb[2 * i + 1]);
        uint4 q;
        __half2 h0 = __floats2half2_rn(v0.x, v0.y);
        __half2 h1 = __floats2half2_rn(v0.z, v0.w);
        __half2 h2 = __floats2half2_rn(v1.x, v1.y);
        __half2 h3 = __floats2half2_rn(v1.z, v1.w);
        q.x = *reinterpret_cast<uint32_t*>(&h0);
        q.y = *reinterpret_cast<uint32_t*>(&h1);
        q.z = *reinterpret_cast<uint32_t*>(&h2);
        q.w = *reinterpret_cast<uint32_t*>(&h3);
        reinterpret_cast<uint4*>(g_embh)[i] = q;
    }
}

// build dense pair table P[i] = (E[i], E[i+1])  (reads the half2 table)
__global__ void __launch_bounds__(256)
pair_kernel(int n)
{
    int i = blockIdx.x * blockDim.x + threadIdx.x;
    if (i < n) {
        uint32_t a = *reinterpret_cast<const uint32_t*>(g_embh + i);
        uint32_t b = *reinterpret_cast<const uint32_t*>(g_embh + i + 1);
        g_paird[i] = make_uint2(a, b);
    }
}

__device__ __forceinline__ uint32_t pick4(uint4 q, uint32_t k)
{
    uint32_t lo = (k & 1u) ? q.y : q.x;
    uint32_t hi = (k & 1u) ? q.w : q.z;
    return (k & 2u) ? hi : lo;
}

__device__ __forceinline__ float2 h2f(uint32_t h)
{
    __half2 v = *reinterpret_cast<__half2*>(&h);
    return __half22float2(v);
}

// Hash-level pair load (R3 structure: 2-way branch, fused quad or 2 singles)
__device__ __forceinline__ void load_pair(uint32_t iA, uint32_t iB,
                                          float2& ea, float2& eb)
{
    uint32_t diff = iA ^ iB;
    if (diff < 4u) {
        uint4 q = __ldg(reinterpret_cast<const uint4*>(g_embh + (iA & ~3u)));
        ea = h2f(pick4(q, iA & 3u));
        eb = h2f(pick4(q, iB & 3u));
    } else {
        ea = h2f(__ldg(reinterpret_cast<const uint32_t*>(g_embh + iA)));
        eb = h2f(__ldg(reinterpret_cast<const uint32_t*>(g_embh + iB)));
    }
}

__global__ void __launch_bounds__(256)
grid_encode_kernel(const float* __restrict__ in,
                   float2* __restrict__ out,
                   int B)
{
    int t = blockIdx.x * blockDim.x + threadIdx.x;
    int p = t >> 4;           // point index
    int l = t & 15;           // level index
    if (p >= B) return;

    // map inputs from [-1,1] to [0,1]
    float x = (in[p * 3 + 0] + 1.0f) * 0.5f;
    float y = (in[p * 3 + 1] + 1.0f) * 0.5f;
    float z = (in[p * 3 + 2] + 1.0f) * 0.5f;

    float scale = c_scale[l];
    float px = fmaf(x, scale, 0.5f);
    float py = fmaf(y, scale, 0.5f);
    float pz = fmaf(z, scale, 0.5f);

    float fx = floorf(px), fy = floorf(py), fz = floorf(pz);
    uint32_t gx = (uint32_t)fx, gy = (uint32_t)fy, gz = (uint32_t)fz;
    float rx = px - fx, ry = py - fy, rz = pz - fz;

    uint32_t off = c_off[l];

    float2 e0, e1, e2c, e3, e4c, e5, e6, e7;

    if (l >= 3) {
        // hash levels: xor hash + fused-quad pair loads
        uint32_t x0 = gx,              x1 = gx + 1u;
        uint32_t y0 = gy * PRIME1,     y1 = (gy + 1u) * PRIME1;
        uint32_t z0 = gz * PRIME2,     z1 = (gz + 1u) * PRIME2;
        uint32_t h00 = y0 ^ z0, h10 = y1 ^ z0, h01 = y0 ^ z1, h11 = y1 ^ z1;
        uint32_t i00a = ((x0 ^ h00) & HASH_MASK) + off;
        uint32_t i00b = ((x1 ^ h00) & HASH_MASK) + off;
        uint32_t i10a = ((x0 ^ h10) & HASH_MASK) + off;
        uint32_t i10b = ((x1 ^ h10) & HASH_MASK) + off;
        uint32_t i01a = ((x0 ^ h01) & HASH_MASK) + off;
        uint32_t i01b = ((x1 ^ h01) & HASH_MASK) + off;
        uint32_t i11a = ((x0 ^ h11) & HASH_MASK) + off;
        uint32_t i11b = ((x1 ^ h11) & HASH_MASK) + off;

        load_pair(i00a, i00b, e0,  e1);
        load_pair(i10a, i10b, e2c, e3);
        load_pair(i01a, i01b, e4c, e5);
        load_pair(i11a, i11b, e6,  e7);
    } else {
        // dense levels: x-pairs are index-adjacent -> one LDG.64 each, no branch
        uint32_t base = c_base[l];
        uint32_t b2 = base * base;
        uint32_t s = gx + gy * base + gz * b2 + off;
        uint2 d0 = __ldg(&g_paird[s]);
        uint2 d1 = __ldg(&g_paird[s + base]);
        uint2 d2 = __ldg(&g_paird[s + b2]);
        uint2 d3 = __ldg(&g_paird[s + base + b2]);
        e0  = h2f(d0.x);  e1 = h2f(d0.y);
        e2c = h2f(d1.x);  e3 = h2f(d1.y);
        e4c = h2f(d2.x);  e5 = h2f(d2.y);
        e6  = h2f(d3.x);  e7 = h2f(d3.y);
    }

    float wx0 = 1.0f - rx, wx1 = rx;
    float wy0 = 1.0f - ry, wy1 = ry;
    float wz0 = 1.0f - rz, wz1 = rz;

    float w00 = wy0 * wz0, w10 = wy1 * wz0, w01 = wy0 * wz1, w11 = wy1 * wz1;

    float w0 = wx0 * w00, w1 = wx1 * w00;
    float w2 = wx0 * w10, w3 = wx1 * w10;
    float w4 = wx0 * w01, w5 = wx1 * w01;
    float w6 = wx0 * w11, w7 = wx1 * w11;

    float a0 = w0 * e0.x;            float a1 = w0 * e0.y;
    a0 = fmaf(w1, e1.x,  a0);        a1 = fmaf(w1, e1.y,  a1);
    a0 = fmaf(w2, e2c.x, a0);        a1 = fmaf(w2, e2c.y, a1);
    a0 = fmaf(w3, e3.x,  a0);        a1 = fmaf(w3, e3.y,  a1);
    a0 = fmaf(w4, e4c.x, a0);        a1 = fmaf(w4, e4c.y, a1);
    a0 = fmaf(w5, e5.x,  a0);        a1 = fmaf(w5, e5.y,  a1);
    a0 = fmaf(w6, e6.x,  a0);        a1 = fmaf(w6, e6.y,  a1);
    a0 = fmaf(w7, e7.x,  a0);        a1 = fmaf(w7, e7.y,  a1);

    out[p * 16 + l] = make_float2(a0, a1);
}

extern "C" void kernel_launch(void* const* d_in, const int* in_sizes, int n_in,
                              void* d_out, int out_size) {
    const float*  inputs = (const float*)d_in[0];       // [B, 3]
    const float4* emb4   = (const float4*)d_in[1];      // fp32 table viewed as float4
    float2*       out    = (float2*)d_out;              // [B, 16] of float2

    int B = in_sizes[0] / 3;

    // 1) fp32 -> half2 table (TOTAL_PARAMS divisible by 4)
    int nquads = TOTAL_PARAMS / 4;
    convert_kernel<<<(nquads + 255) / 256, 256>>>(emb4, nquads);

    // 2) dense pair table
    pair_kernel<<<(DENSE_TOTAL + 255) / 256, 256>>>(DENSE_TOTAL);

    // 3) main encode
    int threads = 256;
    long long total = (long long)B * 16;
    int blocks = (int)((total + threads - 1) / threads);
    grid_encode_kernel<<<blocks, threads>>>(inputs, out, B);
}

// round 7
// speedup vs baseline: 1.2302x; 1.0936x over previous
#include <cuda_runtime.h>
#include <cuda_fp16.h>
#include <cstdint>

// GridEncoder (instant-ngp style), D=3, L=16, C=2, H=16, PLS=2, log2_hashmap=19,
// align_corners=false.
//
// R7 = R6 hash path + dense CELL table:
//   - dense levels (l<3): per-cell 32B record holding all 8 corner half2
//     entries -> 2x LDG.128 from ONE 128B line (2 wavefronts vs 4).
//   - hash levels (l>=3): R3/R6 fused-quad pair loads (75% 1 line, 25% 2).

#define NLEV 16
#define PRIME1 2654435761u
#define PRIME2 805459861u
#define HASH_MASK 0x7FFFFu
#define TOTAL_PARAMS 7131240
#define NCELLS 299008            // 16^3 + 32^3 + 64^3

__device__ __align__(16) __half2 g_embh[TOTAL_PARAMS];   // 28.5 MB half2 table
__device__ __align__(32) uint4   g_celld[2 * NCELLS];    // 9.6 MB dense cell table

__constant__ uint32_t c_off[NLEV] = {
    0u, 4920u, 40864u, 315496u,
    839784u, 1364072u, 1888360u, 2412648u,
    2936936u, 3461224u, 3985512u, 4509800u,
    5034088u, 5558376u, 6082664u, 6606952u
};
__constant__ float c_scale[NLEV] = {
    15.f, 31.f, 63.f, 127.f, 255.f, 511.f, 1023.f, 2047.f,
    4095.f, 8191.f, 16383.f, 32767.f, 65535.f, 131071.f, 262143.f, 524287.f
};
__constant__ uint32_t c_celloff[3] = {0u, 4096u, 36864u};  // cell-table level bases

// fp32 [N,2] -> half2 [N]; 4 entries per thread, one 16B store.
__global__ void __launch_bounds__(256)
convert_kernel(const float4* __restrict__ emb, int nquads)
{
    int i = blockIdx.x * blockDim.x + threadIdx.x;
    if (i < nquads) {
        float4 v0 = __ldg(&emb[2 * i + 0]);
        float4 v1 = __ldg(&emb[2 * i + 1]);
        uint4 q;
        __half2 h0 = __floats2half2_rn(v0.x, v0.y);
        __half2 h1 = __floats2half2_rn(v0.z, v0.w);
        __half2 h2 = __floats2half2_rn(v1.x, v1.y);
        __half2 h3 = __floats2half2_rn(v1.z, v1.w);
        q.x = *reinterpret_cast<uint32_t*>(&h0);
        q.y = *reinterpret_cast<uint32_t*>(&h1);
        q.z = *reinterpret_cast<uint32_t*>(&h2);
        q.w = *reinterpret_cast<uint32_t*>(&h3);
        reinterpret_cast<uint4*>(g_embh)[i] = q;
    }
}

// Build the dense cell table from the half2 table.
// Cell record c: uint4 #0 = {E[s],E[s+1],E[s+b],E[s+b+1]} (z0 plane),
//                uint4 #1 = same at z+1.
__global__ void __launch_bounds__(256)
cell_kernel(int ncells)
{
    int i = blockIdx.x * blockDim.x + threadIdx.x;
    if (i >= ncells) return;

    uint32_t l, lc, sft, base, off;
    if (i < 4096)        { l = 0u; lc = i;          sft = 4u; base = 17u; off = 0u; }
    else if (i < 36864)  { l = 1u; lc = i - 4096;   sft = 5u; base = 33u; off = 4920u; }
    else                 { l = 2u; lc = i - 36864;  sft = 6u; base = 65u; off = 40864u; }
    (void)l;

    uint32_t mask = (1u << sft) - 1u;
    uint32_t gx = lc & mask;
    uint32_t gy = (lc >> sft) & mask;
    uint32_t gz = lc >> (2u * sft);

    uint32_t b2 = base * base;
    uint32_t s = off + gx + gy * base + gz * b2;

    const uint32_t* e = reinterpret_cast<const uint32_t*>(g_embh);
    uint4 qa, qb;
    qa.x = e[s];            qa.y = e[s + 1u];
    qa.z = e[s + base];     qa.w = e[s + base + 1u];
    qb.x = e[s + b2];       qb.y = e[s + b2 + 1u];
    qb.z = e[s + base + b2];qb.w = e[s + base + b2 + 1u];

    g_celld[2 * i + 0] = qa;
    g_celld[2 * i + 1] = qb;
}

__device__ __forceinline__ uint32_t pick4(uint4 q, uint32_t k)
{
    uint32_t lo = (k & 1u) ? q.y : q.x;
    uint32_t hi = (k & 1u) ? q.w : q.z;
    return (k & 2u) ? hi : lo;
}

__device__ __forceinline__ float2 h2f(uint32_t h)
{
    __half2 v = *reinterpret_cast<__half2*>(&h);
    return __half22float2(v);
}

// Hash-level pair load (R3 structure: 2-way branch, fused quad or 2 singles)
__device__ __forceinline__ void load_pair(uint32_t iA, uint32_t iB,
                                          float2& ea, float2& eb)
{
    uint32_t diff = iA ^ iB;
    if (diff < 4u) {
        uint4 q = __ldg(reinterpret_cast<const uint4*>(g_embh + (iA & ~3u)));
        ea = h2f(pick4(q, iA & 3u));
        eb = h2f(pick4(q, iB & 3u));
    } else {
        ea = h2f(__ldg(reinterpret_cast<const uint32_t*>(g_embh + iA)));
        eb = h2f(__ldg(reinterpret_cast<const uint32_t*>(g_embh + iB)));
    }
}

__global__ void __launch_bounds__(256)
grid_encode_kernel(const float* __restrict__ in,
                   float2* __restrict__ out,
                   int B)
{
    int t = blockIdx.x * blockDim.x + threadIdx.x;
    int p = t >> 4;           // point index
    int l = t & 15;           // level index
    if (p >= B) return;

    // map inputs from [-1,1] to [0,1]
    float x = (in[p * 3 + 0] + 1.0f) * 0.5f;
    float y = (in[p * 3 + 1] + 1.0f) * 0.5f;
    float z = (in[p * 3 + 2] + 1.0f) * 0.5f;

    float scale = c_scale[l];
    float px = fmaf(x, scale, 0.5f);
    float py = fmaf(y, scale, 0.5f);
    float pz = fmaf(z, scale, 0.5f);

    float fx = floorf(px), fy = floorf(py), fz = floorf(pz);
    uint32_t gx = (uint32_t)fx, gy = (uint32_t)fy, gz = (uint32_t)fz;
    float rx = px - fx, ry = py - fy, rz = pz - fz;

    float2 e0, e1, e2c, e3, e4c, e5, e6, e7;

    if (l >= 3) {
        uint32_t off = c_off[l];
        uint32_t x0 = gx,              x1 = gx + 1u;
        uint32_t y0 = gy * PRIME1,     y1 = (gy + 1u) * PRIME1;
        uint32_t z0 = gz * PRIME2,     z1 = (gz + 1u) * PRIME2;
        uint32_t h00 = y0 ^ z0, h10 = y1 ^ z0, h01 = y0 ^ z1, h11 = y1 ^ z1;
        uint32_t i00a = ((x0 ^ h00) & HASH_MASK) + off;
        uint32_t i00b = ((x1 ^ h00) & HASH_MASK) + off;
        uint32_t i10a = ((x0 ^ h10) & HASH_MASK) + off;
        uint32_t i10b = ((x1 ^ h10) & HASH_MASK) + off;
        uint32_t i01a = ((x0 ^ h01) & HASH_MASK) + off;
        uint32_t i01b = ((x1 ^ h01) & HASH_MASK) + off;
        uint32_t i11a = ((x0 ^ h11) & HASH_MASK) + off;
        uint32_t i11b = ((x1 ^ h11) & HASH_MASK) + off;

        load_pair(i00a, i00b, e0,  e1);
        load_pair(i10a, i10b, e2c, e3);
        load_pair(i01a, i01b, e4c, e5);
        load_pair(i11a, i11b, e6,  e7);
    } else {
        // dense levels: one 32B cell record -> 2 LDG.128 on the same line
        uint32_t sft = 4u + (uint32_t)l;
        uint32_t cell = c_celloff[l] + gx + (gy << sft) + (gz << (sft + sft));
        const uint4* cp = &g_celld[2u * cell];
        uint4 qa = __ldg(cp);
        uint4 qb = __ldg(cp + 1);
        e0  = h2f(qa.x);  e1 = h2f(qa.y);
        e2c = h2f(qa.z);  e3 = h2f(qa.w);
        e4c = h2f(qb.x);  e5 = h2f(qb.y);
        e6  = h2f(qb.z);  e7 = h2f(qb.w);
    }

    float wx0 = 1.0f - rx, wx1 = rx;
    float wy0 = 1.0f - ry, wy1 = ry;
    float wz0 = 1.0f - rz, wz1 = rz;

    float w00 = wy0 * wz0, w10 = wy1 * wz0, w01 = wy0 * wz1, w11 = wy1 * wz1;

    float w0 = wx0 * w00, w1 = wx1 * w00;
    float w2 = wx0 * w10, w3 = wx1 * w10;
    float w4 = wx0 * w01, w5 = wx1 * w01;
    float w6 = wx0 * w11, w7 = wx1 * w11;

    float a0 = w0 * e0.x;            float a1 = w0 * e0.y;
    a0 = fmaf(w1, e1.x,  a0);        a1 = fmaf(w1, e1.y,  a1);
    a0 = fmaf(w2, e2c.x, a0);        a1 = fmaf(w2, e2c.y, a1);
    a0 = fmaf(w3, e3.x,  a0);        a1 = fmaf(w3, e3.y,  a1);
    a0 = fmaf(w4, e4c.x, a0);        a1 = fmaf(w4, e4c.y, a1);
    a0 = fmaf(w5, e5.x,  a0);        a1 = fmaf(w5, e5.y,  a1);
    a0 = fmaf(w6, e6.x,  a0);        a1 = fmaf(w6, e6.y,  a1);
    a0 = fmaf(w7, e7.x,  a0);        a1 = fmaf(w7, e7.y,  a1);

    out[p * 16 + l] = make_float2(a0, a1);
}

extern "C" void kernel_launch(void* const* d_in, const int* in_sizes, int n_in,
                              void* d_out, int out_size) {
    const float*  inputs = (const float*)d_in[0];       // [B, 3]
    const float4* emb4   = (const float4*)d_in[1];      // fp32 table viewed as float4
    float2*       out    = (float2*)d_out;              // [B, 16] of float2

    int B = in_sizes[0] / 3;

    // 1) fp32 -> half2 table (TOTAL_PARAMS divisible by 4)
    int nquads = TOTAL_PARAMS / 4;
    convert_kernel<<<(nquads + 255) / 256, 256>>>(emb4, nquads);

    // 2) dense cell table (reads half2 table; same stream -> ordered)
    cell_kernel<<<(NCELLS + 255) / 256, 256>>>(NCELLS);

    // 3) main encode
    int threads = 256;
    long long total = (long long)B * 16;
    int blocks = (int)((total + threads - 1) / threads);
    grid_encode_kernel<<<blocks, threads>>>(inputs, out, B);
}